// round 8
// baseline (speedup 1.0000x reference)
#include <cuda_runtime.h>
#include <math.h>
#include <stdint.h>

// FIRE bias: out[1, H=12, S=2048, S=2048] fp32.
// bias[h,s,t] = b2[h] + sum_w w2[h,w] * relu(nd*w1[w] + b1[w])
//   lr[d]  = log((|d|+EPS)*c + LOG_BIAS + EPS)
//   ln[s]  = log(|c*(max(s,thr)+EPS)| + LOG_BIAS + EPS),  thr = |L_mult*init_L|
//   nd     = lr[|s-t|] / ln[s]
// Head MLP is piecewise-linear in nd with 32 hinges at -b1/w1. Setup builds
// per-segment (alpha,beta) per head via an incremental scan over sorted
// hinges; main kernel: binary search + 1 FMA per head, streaming stores.

#define S_LEN 2048
#define H_HEADS 12
#define W_HID 32
#define N_SEG 33            // W_HID + 1
#define EPSF 1e-6f
#define LOG_BIAS_EPS (1.0f + 1e-6f)

__device__ float  g_lr[S_LEN];            // log_rel table by distance d
__device__ float  g_invln[S_LEN];         // 1/log_norm per row s
__device__ float  g_hinge[W_HID];         // sorted hinge values
__device__ float2 g_ab[N_SEG * H_HEADS];  // (alpha, beta) per (segment, head)

// grid = 9 blocks x 256 threads.
// blocks 0..7: fill lr/invln tables (256 entries each).
// block 8: hinges (sorted) + incremental (alpha,beta) scan.
__global__ void fire_setup_kernel(const float* __restrict__ w1,
                                  const float* __restrict__ b1,
                                  const float* __restrict__ w2,
                                  const float* __restrict__ b2,
                                  const float* __restrict__ pc,
                                  const float* __restrict__ pLm,
                                  const float* __restrict__ pL0)
{
    const int tid = threadIdx.x;
    const int bid = blockIdx.x;
    const float c = *pc;

    if (bid < 8) {
        const float thr = fabsf((*pLm) * (*pL0));
        int i = bid * 256 + tid;                   // [0, 2048)
        float ar = fabsf((float)i) + EPSF;
        g_lr[i] = logf(ar * c + LOG_BIAS_EPS);
        float pn = fmaxf((float)i, thr) + EPSF;
        g_invln[i] = 1.0f / logf(fabsf(c * pn) + LOG_BIAS_EPS);
        return;
    }

    // ---- block 8: hinge sort + (alpha,beta) incremental scan ----
    __shared__ float s_w1[W_HID], s_b1[W_HID], s_h[W_HID];
    __shared__ float s_w2[H_HEADS * W_HID];
    __shared__ int   s_order[W_HID];           // s_order[rank] = hinge index

    if (tid < W_HID) { s_w1[tid] = w1[tid]; s_b1[tid] = b1[tid]; }
    // FIX (R5 bug): 384 entries, 256 threads -> grid-stride loop, not a guard.
    for (int i = tid; i < H_HEADS * W_HID; i += blockDim.x) s_w2[i] = w2[i];
    __syncthreads();

    if (tid < W_HID) {
        float w = s_w1[tid];
        // w1==0: relu term is constant in nd; hinge -> +inf so it never ranks
        // below any finite nd (segments beyond finite hinges are unreachable).
        s_h[tid] = (w != 0.0f) ? (-s_b1[tid] / w) : __int_as_float(0x7f800000);
    }
    __syncthreads();

    if (tid < W_HID) {
        float h = s_h[tid];
        int r = 0;
        #pragma unroll
        for (int j = 0; j < W_HID; ++j) {
            float hj = s_h[j];
            r += (hj < h) || (hj == h && j < tid);   // stable 0-based rank
        }
        s_order[r] = tid;
    }
    __syncthreads();

    if (tid < W_HID) g_hinge[tid] = s_h[s_order[tid]];

    if (tid < H_HEADS) {
        const int h = tid;
        // segment 0: active = {w1<0} plus constant terms {w1==0 && b1>0}
        float a = 0.0f;
        float b = b2[h];
        #pragma unroll
        for (int w = 0; w < W_HID; ++w) {
            float ww = s_w1[w];
            float wv = s_w2[h * W_HID + w];
            if (ww < 0.0f) {
                a = fmaf(wv, ww,      a);
                b = fmaf(wv, s_b1[w], b);
            } else if (ww == 0.0f && s_b1[w] > 0.0f) {
                b = fmaf(wv, s_b1[w], b);
            }
        }
        g_ab[0 * H_HEADS + h] = make_float2(a, b);
        // crossing sorted hinge k-1 toggles exactly one unit:
        //   w1>0 : inactive -> active (add);  w1<0 : active -> inactive (sub)
        for (int k = 1; k < N_SEG; ++k) {
            int j = s_order[k - 1];
            float ww = s_w1[j];
            float wv = s_w2[h * W_HID + j];
            float sgn = (ww > 0.0f) ? 1.0f : ((ww < 0.0f) ? -1.0f : 0.0f);
            a = fmaf(sgn * wv, ww,      a);
            b = fmaf(sgn * wv, s_b1[j], b);
            g_ab[k * H_HEADS + h] = make_float2(a, b);
        }
    }
}

__device__ __forceinline__ int seg_search(const float* __restrict__ sh_h, float nd)
{
    // rank = number of sorted hinges <= nd, in [0, 32]
    int k = 0;
    if (sh_h[k + 15] <= nd) k += 16;
    if (sh_h[k + 7]  <= nd) k += 8;
    if (sh_h[k + 3]  <= nd) k += 4;
    if (sh_h[k + 1]  <= nd) k += 2;
    if (sh_h[k]      <= nd) k += 1;
    if (k == 31 && sh_h[31] <= nd) k += 1;   // rank 32: all hinges <= nd
    return k;
}

// 1 block per row s; 256 threads x 8 t-values each.
__global__ __launch_bounds__(256)
void fire_main_kernel(float* __restrict__ out)
{
    __shared__ float  sh_h[W_HID];
    __shared__ float2 sh_ab[N_SEG * H_HEADS];

    const int tid = threadIdx.x;
    if (tid < W_HID) sh_h[tid] = g_hinge[tid];
    for (int i = tid; i < N_SEG * H_HEADS; i += 256) sh_ab[i] = g_ab[i];
    __syncthreads();

    const int s  = blockIdx.x;
    const int t0 = tid * 8;

    const float invln = __ldg(&g_invln[s]);

    float nd[8];
    int   ko[8];                       // k * H_HEADS offsets
    #pragma unroll
    for (int i = 0; i < 8; ++i) {
        int d = abs(s - (t0 + i));
        nd[i] = __ldg(&g_lr[d]) * invln;
    }
    bool same = true;
    #pragma unroll
    for (int i = 0; i < 8; ++i) {
        int k = seg_search(sh_h, nd[i]);
        ko[i] = k * H_HEADS;
        if (i > 0) same &= (ko[i] == ko[0]);
    }

    const size_t plane = (size_t)S_LEN * S_LEN;
    float* __restrict__ p = out + (size_t)s * S_LEN + t0;

    // warp-uniform branch; each thread still uses its own segment row
    bool uni = __all_sync(0xffffffffu, same);

    if (uni) {
        const float2* __restrict__ row = &sh_ab[ko[0]];
        #pragma unroll
        for (int h = 0; h < H_HEADS; ++h) {
            float2 ab = row[h];
            float4 v0, v1;
            v0.x = fmaf(ab.x, nd[0], ab.y);
            v0.y = fmaf(ab.x, nd[1], ab.y);
            v0.z = fmaf(ab.x, nd[2], ab.y);
            v0.w = fmaf(ab.x, nd[3], ab.y);
            v1.x = fmaf(ab.x, nd[4], ab.y);
            v1.y = fmaf(ab.x, nd[5], ab.y);
            v1.z = fmaf(ab.x, nd[6], ab.y);
            v1.w = fmaf(ab.x, nd[7], ab.y);
            float4* dst = reinterpret_cast<float4*>(p + (size_t)h * plane);
            __stcs(dst,     v0);
            __stcs(dst + 1, v1);
        }
    } else {
        #pragma unroll
        for (int h = 0; h < H_HEADS; ++h) {
            float r[8];
            #pragma unroll
            for (int i = 0; i < 8; ++i) {
                float2 ab = sh_ab[ko[i] + h];
                r[i] = fmaf(ab.x, nd[i], ab.y);
            }
            float4 v0 = make_float4(r[0], r[1], r[2], r[3]);
            float4 v1 = make_float4(r[4], r[5], r[6], r[7]);
            float4* dst = reinterpret_cast<float4*>(p + (size_t)h * plane);
            __stcs(dst,     v0);
            __stcs(dst + 1, v1);
        }
    }
}

extern "C" void kernel_launch(void* const* d_in, const int* in_sizes, int n_in,
                              void* d_out, int out_size)
{
    // inputs (metadata order): x, w1, b1, w2, b2, c, L_multiplier, init_L
    const float* w1 = (const float*)d_in[1];
    const float* b1 = (const float*)d_in[2];
    const float* w2 = (const float*)d_in[3];
    const float* b2 = (const float*)d_in[4];
    const float* c  = (const float*)d_in[5];
    const float* Lm = (const float*)d_in[6];
    const float* L0 = (const float*)d_in[7];
    float* out = (float*)d_out;

    fire_setup_kernel<<<9, 256>>>(w1, b1, w2, b2, c, Lm, L0);
    fire_main_kernel<<<S_LEN, 256>>>(out);
}